// round 8
// baseline (speedup 1.0000x reference)
#include <cuda_runtime.h>
#include <math.h>
#include <stdint.h>

// Problem: B=64, T=1024, D=512, H=512
//   xw = x @ W[:512] + b              (65536x512x512 GEMM)
//   h_t = tanh(xw_t + h_{t-1} @ Wh)   scan over T=1024
//
// Phase 1: FFMA2 (packed f32x2) tiled GEMM -> g_xw scratch
// Phase 2: 16 groups x 8 CTAs (no clusters). CTA = 4 rows x 64 cols.
//   h exchange through L2 as SELF-VALIDATING 8B atoms {f32 value, u32 tag}.
//   R8: sentinel-first polling (1 load/warp/round during the wait, then one
//   validated bulk load) so the polls no longer saturate LTS; h published
//   before the out STG; tree reduction.

__device__ float g_xw[64u * 1024u * 512u];  // 128 MB scratch: [b][t][h]
// [buf][group][producerCTA][feature(64)][row(4)] : {f32 val, u32 tag}
__device__ unsigned long long g_hx[2][16][8][64][4];  // 512 KB

#define FMA2(d, a, b, c) \
    asm("fma.rn.f32x2 %0, %1, %2, %3;" : "=l"(d) : "l"(a), "l"(b), "l"(c))
#define ADDF2(d, a, b) \
    asm("add.rn.f32x2 %0, %1, %2;" : "=l"(d) : "l"(a), "l"(b))
#define PACK2(d, lo, hi) \
    asm("mov.b64 %0, {%1, %2};" : "=l"(d) : "f"(lo), "f"(hi))
#define UNPACK2(lo, hi, v) \
    asm("mov.b64 {%0, %1}, %2;" : "=f"(lo), "=f"(hi) : "l"(v))

// ---------------------------------------------------------------------------
// Phase 1: g_xw[m][n] = sum_k x[m][k] * W[k][n] + b[n]
// ---------------------------------------------------------------------------
__global__ __launch_bounds__(256) void xw_gemm(const float* __restrict__ x,
                                               const float* __restrict__ W,
                                               const float* __restrict__ bias) {
    __shared__ __align__(16) float Ast[16][132];
    __shared__ __align__(16) float Bs[16][128];

    const int tid = threadIdx.x;
    const int bn = blockIdx.x & 3;
    const int bm = blockIdx.x >> 2;
    const int row0 = bm << 7;
    const int n0 = bn << 7;
    const int mt = tid >> 4;
    const int nt = tid & 15;

    unsigned long long acc[4][8];
#pragma unroll
    for (int p = 0; p < 4; p++)
#pragma unroll
        for (int j = 0; j < 8; j++) acc[p][j] = 0ULL;

    for (int kt = 0; kt < 512; kt += 16) {
#pragma unroll
        for (int it = 0; it < 2; it++) {
            int idx = tid + (it << 8);
            int m = idx >> 2;
            int kq = (idx & 3) << 2;
            float4 v = *(const float4*)(x + (size_t)(row0 + m) * 512 + kt + kq);
            Ast[kq + 0][m] = v.x;
            Ast[kq + 1][m] = v.y;
            Ast[kq + 2][m] = v.z;
            Ast[kq + 3][m] = v.w;
        }
#pragma unroll
        for (int it = 0; it < 2; it++) {
            int idx = tid + (it << 8);
            int k = idx >> 5;
            int nq = (idx & 31) << 2;
            *(float4*)(&Bs[k][nq]) =
                *(const float4*)(W + (size_t)(kt + k) * 512 + n0 + nq);
        }
        __syncthreads();
#pragma unroll
        for (int k = 0; k < 16; k++) {
            ulonglong2 aA = *(const ulonglong2*)(&Ast[k][4 * mt]);
            ulonglong2 aB = *(const ulonglong2*)(&Ast[k][64 + 4 * mt]);
            float4 b0 = *(const float4*)(&Bs[k][4 * nt]);
            float4 b1 = *(const float4*)(&Bs[k][64 + 4 * nt]);
            unsigned long long bb[8];
            PACK2(bb[0], b0.x, b0.x);
            PACK2(bb[1], b0.y, b0.y);
            PACK2(bb[2], b0.z, b0.z);
            PACK2(bb[3], b0.w, b0.w);
            PACK2(bb[4], b1.x, b1.x);
            PACK2(bb[5], b1.y, b1.y);
            PACK2(bb[6], b1.z, b1.z);
            PACK2(bb[7], b1.w, b1.w);
#pragma unroll
            for (int j = 0; j < 8; j++) {
                FMA2(acc[0][j], aA.x, bb[j], acc[0][j]);
                FMA2(acc[1][j], aA.y, bb[j], acc[1][j]);
                FMA2(acc[2][j], aB.x, bb[j], acc[2][j]);
                FMA2(acc[3][j], aB.y, bb[j], acc[3][j]);
            }
        }
        __syncthreads();
    }

    float bv[8];
#pragma unroll
    for (int j = 0; j < 4; j++) {
        bv[j] = bias[n0 + 4 * nt + j];
        bv[4 + j] = bias[n0 + 64 + 4 * nt + j];
    }
    float res[8][8];
#pragma unroll
    for (int p = 0; p < 4; p++)
#pragma unroll
        for (int j = 0; j < 8; j++) {
            float lo, hi;
            UNPACK2(lo, hi, acc[p][j]);
            res[2 * p][j] = lo + bv[j];
            res[2 * p + 1][j] = hi + bv[j];
        }
#pragma unroll
    for (int rI = 0; rI < 8; rI++) {
        int lrow = (rI < 4) ? (4 * mt + rI) : (64 + 4 * mt + (rI - 4));
        size_t base = (size_t)(row0 + lrow) * 512 + n0;
        float4 s0 = make_float4(res[rI][0], res[rI][1], res[rI][2], res[rI][3]);
        float4 s1 = make_float4(res[rI][4], res[rI][5], res[rI][6], res[rI][7]);
        *(float4*)(g_xw + base + 4 * nt) = s0;
        *(float4*)(g_xw + base + 64 + 4 * nt) = s1;
    }
}

// ---------------------------------------------------------------------------
// zero the tag arena (must run each replay so stale tags never match)
// ---------------------------------------------------------------------------
__global__ void init_hx() {
    unsigned long long* p = &g_hx[0][0][0][0][0];
    int i = blockIdx.x * blockDim.x + threadIdx.x;
#pragma unroll
    for (int q = 0; q < 4; q++) p[i + q * 16384] = 0ULL;
}

// ---------------------------------------------------------------------------
// Phase 2: tagged-value scan with sentinel-first polling.
// ---------------------------------------------------------------------------
__global__ __launch_bounds__(256, 1) void rnn_scan(const float* __restrict__ W,
                                                   float* __restrict__ out) {
    __shared__ __align__(16) float dupA[8][64][4];                 // 8 KB
    __shared__ __align__(16) float dupB[8][64][4];                 // 8 KB
    __shared__ __align__(16) unsigned long long red[2][8][4][66];  // 33 KB

    const int bid = blockIdx.x;
    const int g = bid >> 3;   // group 0..15
    const int r0 = g << 2;    // 4 batch rows
    const int s = bid & 7;    // col split 0..7
    const int c0 = s << 6;    // 64 feature cols
    const int tid = threadIdx.x;
    const int cp = tid & 31;  // col-pair lane
    const int ks = tid >> 5;  // warp id == producer CTA watched

    // Wh slice: wpk[j] = {W[512+64ks+j][c0+2cp], W[512+64ks+j][c0+2cp+1]}
    unsigned long long wpk[64];
#pragma unroll
    for (int j = 0; j < 64; j++) {
        float2 w2 = *(const float2*)&W[(size_t)(512 + (ks << 6) + j) * 512 +
                                       c0 + (cp << 1)];
        PACK2(wpk[j], w2.x, w2.y);
    }

    const int rr = tid >> 6;  // epilogue row 0..3
    const int cc = tid & 63;  // epilogue col 0..63

    // poll sources: slots [buf][g][ks][cp][0..3] and [cp+32][0..3]
    unsigned long long* const src0 = &g_hx[0][g][ks][cp][0];
    unsigned long long* const src1 = &g_hx[0][g][ks][cp + 32][0];
    const size_t bufstride = 16 * 8 * 64 * 4;  // u64s per buffer

    // publish target: [buf][g][s][cc][rr]
    unsigned long long* const dst = &g_hx[0][g][s][cc][rr];

    for (int t = 0; t < 1024; t++) {
        const int pb = t & 1;
        // xw prefetch — overlaps poll + dup + mainloop
        float xwv =
            g_xw[((size_t)(r0 + rr) * 1024 + (size_t)t) * 512 + c0 + cc];

        unsigned long long a0 = 0ULL, a1 = 0ULL, a2 = 0ULL, a3 = 0ULL;
        if (t > 0) {
            const unsigned long long* p0 = src0 + (size_t)pb * bufstride;
            const unsigned long long* p1 = src1 + (size_t)pb * bufstride;
            const unsigned int tg = (unsigned int)t;

            // ---- sentinel phase: 1 x 8B load per warp per round ----------
            unsigned int stag;
            do {
                unsigned long long sv0 = 0ULL;
                if (cp == 0) {
                    asm volatile("ld.relaxed.gpu.global.b64 %0, [%1];"
                                 : "=l"(sv0)
                                 : "l"(p0)
                                 : "memory");
                }
                stag = __shfl_sync(0xffffffffu, (unsigned int)(sv0 >> 32), 0);
            } while (stag != tg);

            // ---- bulk phase: validated 2KB load (loop-back on stale) -----
            unsigned long long sv[8];
#pragma unroll
            for (int i = 0; i < 4; i++) {
                asm volatile("ld.relaxed.gpu.global.b64 %0, [%1];"
                             : "=l"(sv[i]) : "l"(p0 + i) : "memory");
                asm volatile("ld.relaxed.gpu.global.b64 %0, [%1];"
                             : "=l"(sv[4 + i]) : "l"(p1 + i) : "memory");
            }
            bool ok;
            do {
                ok = true;
#pragma unroll
                for (int i = 0; i < 4; i++) {
                    if ((unsigned int)(sv[i] >> 32) != tg) {
                        asm volatile("ld.relaxed.gpu.global.b64 %0, [%1];"
                                     : "=l"(sv[i]) : "l"(p0 + i) : "memory");
                        ok = false;
                    }
                    if ((unsigned int)(sv[4 + i] >> 32) != tg) {
                        asm volatile("ld.relaxed.gpu.global.b64 %0, [%1];"
                                     : "=l"(sv[4 + i]) : "l"(p1 + i)
                                     : "memory");
                        ok = false;
                    }
                }
            } while (!ok);

            // dup-expand {h0..h3} -> {h,h} broadcast form
            float h0 = __uint_as_float((unsigned int)sv[0]);
            float h1 = __uint_as_float((unsigned int)sv[1]);
            float h2 = __uint_as_float((unsigned int)sv[2]);
            float h3 = __uint_as_float((unsigned int)sv[3]);
            *(float4*)&dupA[ks][cp][0] = make_float4(h0, h0, h1, h1);
            *(float4*)&dupB[ks][cp][0] = make_float4(h2, h2, h3, h3);
            h0 = __uint_as_float((unsigned int)sv[4]);
            h1 = __uint_as_float((unsigned int)sv[5]);
            h2 = __uint_as_float((unsigned int)sv[6]);
            h3 = __uint_as_float((unsigned int)sv[7]);
            *(float4*)&dupA[ks][cp + 32][0] = make_float4(h0, h0, h1, h1);
            *(float4*)&dupB[ks][cp + 32][0] = make_float4(h2, h2, h3, h3);
            __syncwarp();

            // mainloop: 64 x (2 LDS.128 broadcast + 4 FFMA2)
#pragma unroll
            for (int j = 0; j < 64; j++) {
                ulonglong2 h01 = *(const ulonglong2*)&dupA[ks][j][0];
                ulonglong2 h23 = *(const ulonglong2*)&dupB[ks][j][0];
                FMA2(a0, h01.x, wpk[j], a0);  // row 0 {c_e,c_o}
                FMA2(a1, h01.y, wpk[j], a1);  // row 1
                FMA2(a2, h23.x, wpk[j], a2);  // row 2
                FMA2(a3, h23.y, wpk[j], a3);  // row 3
            }
        }
        // cross-k-chunk reduction (double-buffered -> one barrier per step)
        red[pb][ks][0][cp] = a0;
        red[pb][ks][1][cp] = a1;
        red[pb][ks][2][cp] = a2;
        red[pb][ks][3][cp] = a3;
        __syncthreads();

        // tree reduction over the 8 k-chunks
        unsigned long long q0, q1, q2, q3;
        ADDF2(q0, red[pb][0][rr][cc >> 1], red[pb][1][rr][cc >> 1]);
        ADDF2(q1, red[pb][2][rr][cc >> 1], red[pb][3][rr][cc >> 1]);
        ADDF2(q2, red[pb][4][rr][cc >> 1], red[pb][5][rr][cc >> 1]);
        ADDF2(q3, red[pb][6][rr][cc >> 1], red[pb][7][rr][cc >> 1]);
        ADDF2(q0, q0, q1);
        ADDF2(q2, q2, q3);
        ADDF2(q0, q0, q2);
        float slo, shi;
        UNPACK2(slo, shi, q0);
        float v = tanhf(xwv + ((cc & 1) ? shi : slo));

        if (t < 1023) {
            // publish tagged h FIRST — the recurrence-critical store
            unsigned long long pkt =
                ((unsigned long long)(unsigned int)(t + 1) << 32) |
                (unsigned long long)__float_as_uint(v);
            unsigned long long* d = dst + (size_t)((t + 1) & 1) * bufstride;
            asm volatile("st.relaxed.gpu.global.b64 [%0], %1;" ::"l"(d),
                         "l"(pkt)
                         : "memory");
        }
        out[((size_t)(r0 + rr) * 1024 + (size_t)t) * 512 + c0 + cc] = v;
    }
}

// ---------------------------------------------------------------------------
extern "C" void kernel_launch(void* const* d_in, const int* in_sizes, int n_in,
                              void* d_out, int out_size) {
    const float* x = (const float*)d_in[0];  // (64, 1024, 512) f32
    const float* W = (const float*)d_in[1];  // (1024, 512) f32
    const float* b = (const float*)d_in[2];  // (512,) f32
    float* out = (float*)d_out;              // (64, 1024, 512) f32

    xw_gemm<<<2048, 256>>>(x, W, b);
    init_hx<<<64, 256>>>();
    rnn_scan<<<128, 256>>>(W, out);
}